// round 5
// baseline (speedup 1.0000x reference)
#include <cuda_runtime.h>

// VolGeoNet trilinear interpolation.
// Strategy: Morton-bin points into 2x2x2-cell bins; one CTA per bin loads the
// bin's 3x3x3 = 27 vertex feature rows (27 KB) into shared memory ONCE, then
// all points in the bin interpolate from smem. This cuts L2->L1 gather traffic
// from 8 KB/point (2.1 GB) to 27 KB/bin (0.89 GB).
//
// x:            (B, 3) float32
// grid_value:   (65^3, 1) float32
// grid_feature: (65^3, 256) float32
// outputs (concatenated in d_out): out (B,1) then feat (B,256)

#define N_GRID 64
#define N1     65
#define W_FEAT 256
#define B_MAX  262144
#define NBINS  32768      // 32^3 bins of 2x2x2 cells, Morton ordered

__device__ int g_counts[NBINS];
__device__ int g_offsets[NBINS];
__device__ int g_cursor[NBINS];
__device__ int g_perm[B_MAX];
__device__ unsigned short g_bins[B_MAX];

__device__ __forceinline__ unsigned spread3(unsigned v) {
    v &= 0x3FF;
    v = (v | (v << 16)) & 0x30000FF;
    v = (v | (v << 8))  & 0x300F00F;
    v = (v | (v << 4))  & 0x30C30C3;
    v = (v | (v << 2))  & 0x9249249;
    return v;
}

__device__ __forceinline__ unsigned compact3(unsigned v) {
    v &= 0x9249249;
    v = (v | (v >> 2))  & 0x30C30C3;
    v = (v | (v >> 4))  & 0x300F00F;
    v = (v | (v >> 8))  & 0x30000FF;
    v = (v | (v >> 16)) & 0x3FF;
    return v;
}

__device__ __forceinline__ int point_bin(const float* __restrict__ x, int p) {
    const float rx = (x[p * 3 + 0] + 1.0f) * 32.0f;
    const float ry = (x[p * 3 + 1] + 1.0f) * 32.0f;
    const float rz = (x[p * 3 + 2] + 1.0f) * 32.0f;
    int ix = min(max(__float2int_rd(rx), 0), N_GRID - 1);
    int iy = min(max(__float2int_rd(ry), 0), N_GRID - 1);
    int iz = min(max(__float2int_rd(rz), 0), N_GRID - 1);
    unsigned bx = (unsigned)(ix >> 1), by = (unsigned)(iy >> 1), bz = (unsigned)(iz >> 1);
    return (int)(spread3(bx) | (spread3(by) << 1) | (spread3(bz) << 2));
}

__global__ void zero_counts_kernel() {
    int i = blockIdx.x * blockDim.x + threadIdx.x;
    if (i < NBINS) g_counts[i] = 0;
}

__global__ void hist_kernel(const float* __restrict__ x, int B) {
    int p = blockIdx.x * blockDim.x + threadIdx.x;
    if (p >= B) return;
    int bin = point_bin(x, p);
    g_bins[p] = (unsigned short)bin;
    atomicAdd(&g_counts[bin], 1);
}

// Single-block exclusive scan over NBINS = 32768 = 1024 threads x 32 elems.
__global__ __launch_bounds__(1024)
void scan_kernel() {
    __shared__ int partial[1024];
    const int t = threadIdx.x;
    const int base = t * 32;

    int local[32];
    int s = 0;
    #pragma unroll
    for (int i = 0; i < 32; i++) {
        local[i] = g_counts[base + i];
        s += local[i];
    }
    partial[t] = s;
    __syncthreads();

    for (int off = 1; off < 1024; off <<= 1) {
        int v = (t >= off) ? partial[t - off] : 0;
        __syncthreads();
        partial[t] += v;
        __syncthreads();
    }

    int excl = (t > 0) ? partial[t - 1] : 0;
    #pragma unroll
    for (int i = 0; i < 32; i++) {
        g_offsets[base + i] = excl;
        g_cursor[base + i]  = excl;
        excl += local[i];
    }
}

__global__ void scatter_kernel(int B) {
    int p = blockIdx.x * blockDim.x + threadIdx.x;
    if (p >= B) return;
    int bin = (int)g_bins[p];
    int pos = atomicAdd(&g_cursor[bin], 1);
    g_perm[pos] = p;
}

// One CTA per bin. 256 threads. Smem: 27 vertex rows x 256 floats = 27 KB.
__global__ __launch_bounds__(256, 8)
void trilerp_bin_kernel(const float* __restrict__ x,
                        const float* __restrict__ gval,
                        const float* __restrict__ gfeat,
                        float* __restrict__ out_val,
                        float* __restrict__ out_feat)
{
    __shared__ float4 s_feat[27 * 64];   // [row][lane64]
    __shared__ float  s_val[27];

    const int bin   = blockIdx.x;
    const int start = g_offsets[bin];
    const int count = g_counts[bin];
    if (count == 0) return;

    const int tid    = threadIdx.x;
    const int lane64 = tid & 63;
    const int sub    = tid >> 6;          // 0..3: which point in the 4-point group

    // Decode Morton bin id -> bin coords (each in [0,32))
    const int bx = (int)compact3((unsigned)bin);
    const int by = (int)compact3((unsigned)bin >> 1);
    const int bz = (int)compact3((unsigned)bin >> 2);
    const int vx0 = bx * 2, vy0 = by * 2, vz0 = bz * 2;   // min vertex of the 3x3x3 block

    // Cooperative load of 27 rows (27*64 float4 = 1728 float4s) into smem.
    #pragma unroll
    for (int i = tid; i < 27 * 64; i += 256) {
        const int r = i >> 6;
        const int l = i & 63;
        const int cx = r / 9, cy = (r / 3) % 3, cz = r % 3;
        const int flat = ((vx0 + cx) * N1 + (vy0 + cy)) * N1 + (vz0 + cz);
        s_feat[i] = __ldg(reinterpret_cast<const float4*>(gfeat + (size_t)flat * W_FEAT) + l);
    }
    if (tid < 27) {
        const int cx = tid / 9, cy = (tid / 3) % 3, cz = tid % 3;
        const int flat = ((vx0 + cx) * N1 + (vy0 + cy)) * N1 + (vz0 + cz);
        s_val[tid] = __ldg(gval + flat);
    }
    __syncthreads();

    // Process points in groups of 4 (64 threads per point).
    for (int i = sub; i < count; i += 4) {
        const int point = g_perm[start + i];

        const float rx = (__ldg(x + point * 3 + 0) + 1.0f) * 32.0f;
        const float ry = (__ldg(x + point * 3 + 1) + 1.0f) * 32.0f;
        const float rz = (__ldg(x + point * 3 + 2) + 1.0f) * 32.0f;

        const bool valid = (rx >= 0.0f) & (rx <= 64.0f) &
                           (ry >= 0.0f) & (ry <= 64.0f) &
                           (rz >= 0.0f) & (rz <= 64.0f);

        float4 acc = make_float4(0.0f, 0.0f, 0.0f, 0.0f);
        float  accv = 0.0f;

        if (valid) {
            const int ix = min(max(__float2int_rd(rx), 0), N_GRID - 1);
            const int iy = min(max(__float2int_rd(ry), 0), N_GRID - 1);
            const int iz = min(max(__float2int_rd(rz), 0), N_GRID - 1);

            const float tx = rx - (float)ix;
            const float ty = ry - (float)iy;
            const float tz = rz - (float)iz;

            const int lx = ix - vx0;   // 0 or 1
            const int ly = iy - vy0;
            const int lz = iz - vz0;
            const int lbase = (lx * 3 + ly) * 3 + lz;   // local row of corner (0,0,0)

            const float wx0 = 1.0f - tx, wx1 = tx;
            const float wy0 = 1.0f - ty, wy1 = ty;
            const float wz0 = 1.0f - tz, wz1 = tz;

            float w[8];
            w[0] = wx0 * wy0 * wz0;
            w[1] = wx0 * wy0 * wz1;
            w[2] = wx0 * wy1 * wz0;
            w[3] = wx0 * wy1 * wz1;
            w[4] = wx1 * wy0 * wz0;
            w[5] = wx1 * wy0 * wz1;
            w[6] = wx1 * wy1 * wz0;
            w[7] = wx1 * wy1 * wz1;

            const int loff[8] = { 0, 1, 3, 4, 9, 10, 12, 13 };  // (ox*3+oy)*3+oz

            #pragma unroll
            for (int c = 0; c < 8; c++) {
                const int r = lbase + loff[c];
                const float wc = w[c];
                const float4 v = s_feat[r * 64 + lane64];
                acc.x = fmaf(wc, v.x, acc.x);
                acc.y = fmaf(wc, v.y, acc.y);
                acc.z = fmaf(wc, v.z, acc.z);
                acc.w = fmaf(wc, v.w, acc.w);
                if (lane64 == 0) accv = fmaf(wc, s_val[r], accv);
            }
        }

        // Streaming stores (evict-first): don't pollute L2's grid working set.
        __stcs(reinterpret_cast<float4*>(out_feat + (size_t)point * W_FEAT) + lane64, acc);
        if (lane64 == 0) __stcs(out_val + point, accv);
    }
}

extern "C" void kernel_launch(void* const* d_in, const int* in_sizes, int n_in,
                              void* d_out, int out_size)
{
    const float* x     = (const float*)d_in[0];
    const float* gval  = (const float*)d_in[1];
    const float* gfeat = (const float*)d_in[2];

    const int B = in_sizes[0] / 3;

    float* out_val  = (float*)d_out;        // (B, 1)
    float* out_feat = (float*)d_out + B;    // (B, 256)

    zero_counts_kernel<<<(NBINS + 255) / 256, 256>>>();
    hist_kernel<<<(B + 255) / 256, 256>>>(x, B);
    scan_kernel<<<1, 1024>>>();
    scatter_kernel<<<(B + 255) / 256, 256>>>(B);

    trilerp_bin_kernel<<<NBINS, 256>>>(x, gval, gfeat, out_val, out_feat);
}